// round 11
// baseline (speedup 1.0000x reference)
#include <cuda_runtime.h>
#include <cuda_fp16.h>
#include <cstdint>

// Causal SDPA: B=2, H=16, S=2048, D=128, fp32 in/out.
// R11 (base = R8, best mapping): latency attack.
//   - P stays in registers: S C-fragments repacked directly as PV A-fragments
//     (no smem round-trip, no __syncwarp, dependency chain shortened)
//   - base-2 softmax: log2(e) folded into Q scale, exp via single-MUFU ex2
//   - 3 CTAs/SM (__launch_bounds__(128,3)): 12 warps to hide chain latency
//   - fp16 m16n8k16 mma w/ f32 accum, ldmatrix K/V, cp.async double buffer,
//     fused prologue (K->fp16, V->fp16 transposed per head)

#define B_ 2
#define H_ 16
#define S_ 2048
#define D_ 128

constexpr int BR      = 64;
constexpr int BC      = 64;
constexpr int THREADS = 128;

// smem row strides in 32-bit words; stride % 32 == 4 -> ldmatrix phases
// cover all 32 banks (conflict-free).
constexpr int KSTW = 68;   // K tile row: 128 halfs + pad
constexpr int VSTW = 36;   // VT tile row: 64 halfs + pad

constexpr int KTILE_W = BC * KSTW;             // 4352 words / stage
constexpr int VTILE_W = D_ * VSTW;             // 4608 words / stage
constexpr int SMEM_WORDS = 2 * KTILE_W + 2 * VTILE_W;   // 17920
constexpr int SMEM_BYTES = SMEM_WORDS * 4;              // 71680 B -> 3 CTAs/SM

constexpr int KV_ELEMS = B_ * H_ * S_ * D_;

__device__ __align__(16) __half g_kth[KV_ELEMS];   // K fp16 [bh][s][d]
__device__ __align__(16) __half g_vth[KV_ELEMS];   // V fp16 transposed [bh][d][s]

// ---------------------------------------------------------------------------
// Fused prologue (unchanged): V->fp16 transposed tile + K->fp16 slice.
// ---------------------------------------------------------------------------
__global__ void __launch_bounds__(256)
prep_kv_kernel(const float* __restrict__ v, const float4* __restrict__ k) {
    __shared__ __half tile[64][65];
    const int bh = blockIdx.z;
    const int s0 = blockIdx.x * 64;
    const int d0 = blockIdx.y * 64;
    const float* vp = v + (long)bh * S_ * D_;
    __half* vtp = g_vth + (long)bh * (long)D_ * S_;

    const int tx = threadIdx.x & 15;
    const int ty = threadIdx.x >> 4;
    #pragma unroll
    for (int p = 0; p < 4; ++p) {
        int si = ty + p * 16;
        float4 a = *(const float4*)(vp + (long)(s0 + si) * D_ + d0 + tx * 4);
        tile[si][tx * 4 + 0] = __float2half_rn(a.x);
        tile[si][tx * 4 + 1] = __float2half_rn(a.y);
        tile[si][tx * 4 + 2] = __float2half_rn(a.z);
        tile[si][tx * 4 + 3] = __float2half_rn(a.w);
    }
    {
        const long nblk = (long)gridDim.x * gridDim.y * gridDim.z;
        const long bid  = (long)(blockIdx.z * gridDim.y + blockIdx.y) * gridDim.x
                        + blockIdx.x;
        const long per  = (KV_ELEMS / 4) / nblk;
        uint2* kd = reinterpret_cast<uint2*>(g_kth);
        long i0 = bid * per;
        for (long i = i0 + threadIdx.x; i < i0 + per; i += 256) {
            float4 a = k[i];
            __half2 lo = __floats2half2_rn(a.x, a.y);
            __half2 hi = __floats2half2_rn(a.z, a.w);
            uint2 o;
            o.x = *(uint32_t*)&lo;
            o.y = *(uint32_t*)&hi;
            kd[i] = o;
        }
    }
    __syncthreads();
    const int lane = threadIdx.x & 31;
    const int w    = threadIdx.x >> 5;
    #pragma unroll
    for (int p = 0; p < 8; ++p) {
        int di = w + p * 8;
        __half2 h = __halves2half2(tile[2 * lane][di], tile[2 * lane + 1][di]);
        *(__half2*)(vtp + (long)(d0 + di) * S_ + s0 + 2 * lane) = h;
    }
}

// ---------------------------------------------------------------------------
__device__ __forceinline__ void mma_f16(float c[4],
                                        uint32_t a0, uint32_t a1, uint32_t a2, uint32_t a3,
                                        uint32_t b0, uint32_t b1) {
    asm volatile(
        "mma.sync.aligned.m16n8k16.row.col.f32.f16.f16.f32 "
        "{%0,%1,%2,%3}, {%4,%5,%6,%7}, {%8,%9}, {%0,%1,%2,%3};"
        : "+f"(c[0]), "+f"(c[1]), "+f"(c[2]), "+f"(c[3])
        : "r"(a0), "r"(a1), "r"(a2), "r"(a3), "r"(b0), "r"(b1));
}
__device__ __forceinline__ void ldsm4(uint32_t& r0, uint32_t& r1,
                                      uint32_t& r2, uint32_t& r3, uint32_t addr) {
    asm volatile("ldmatrix.sync.aligned.m8n8.x4.shared.b16 {%0,%1,%2,%3}, [%4];"
                 : "=r"(r0), "=r"(r1), "=r"(r2), "=r"(r3) : "r"(addr));
}
__device__ __forceinline__ void cp_async16(uint32_t dst, const void* src) {
    asm volatile("cp.async.cg.shared.global [%0], [%1], 16;" :: "r"(dst), "l"(src));
}
__device__ __forceinline__ uint32_t pack2(float a, float b) {
    __half2 h = __floats2half2_rn(a, b);
    return *(uint32_t*)&h;
}
__device__ __forceinline__ float ex2(float x) {   // single MUFU
    float r;
    asm("ex2.approx.ftz.f32 %0, %1;" : "=f"(r) : "f"(x));
    return r;
}

// Load one K tile (BC x 128 halfs) + one VT tile (128 x BC halfs).
__device__ __forceinline__ void load_kv_tile(const __half* kg, const __half* vtg,
                                             uint32_t kdst, uint32_t vdst, int tid) {
    #pragma unroll
    for (int it = 0; it < (BC * 16) / THREADS; ++it) {
        int i = tid + it * THREADS;
        int row = i >> 4, ch = i & 15;
        cp_async16(kdst + (uint32_t)(row * KSTW + ch * 4) * 4u, kg + row * D_ + ch * 8);
    }
    #pragma unroll
    for (int it = 0; it < (D_ * 8) / THREADS; ++it) {
        int i = tid + it * THREADS;
        int row = i >> 3, ch = i & 7;
        cp_async16(vdst + (uint32_t)(row * VSTW + ch * 4) * 4u, vtg + (long)row * S_ + ch * 8);
    }
    asm volatile("cp.async.commit_group;");
}

__global__ __launch_bounds__(THREADS, 3)
void fa_regp_kernel(const float* __restrict__ q, float* __restrict__ out) {
    extern __shared__ __align__(16) uint32_t smem[];

    const int tid  = threadIdx.x;
    const int w    = tid >> 5;
    const int lane = tid & 31;
    const int g    = lane >> 2;   // group id (rows g, g+8 of mma tile)
    const int c    = lane & 3;    // thread-in-group

    // ldmatrix per-lane row/selector decomposition
    const int r8 = lane & 7;
    const int s3 = (lane >> 3) & 1;
    const int s4 = lane >> 4;

    // longest-running q-tiles launch first
    const int qt     = (int)(gridDim.x - 1) - (int)blockIdx.x;
    const int bh     = blockIdx.y;
    const long base  = (long)bh * S_ * D_;
    const int q_base = qt * BR;
    const int njt    = (q_base + BR) / BC;
    const int wrow   = q_base + w * 16;

    // D^-0.5 * log2(e): softmax runs in base-2 (ex2 = single MUFU op)
    const float scale = 0.08838834764831845f * 1.4426950408889634f;

    const uint32_t smem_u32 = (uint32_t)__cvta_generic_to_shared(smem);
    const uint32_t k_u32    = smem_u32;
    const uint32_t v_u32    = smem_u32 + (uint32_t)(2 * KTILE_W) * 4u;

    const uint32_t koff = (uint32_t)(r8 * KSTW + s4 * 8 + s3 * 4) * 4u;
    const uint32_t voff = (uint32_t)(r8 * VSTW + s4 * 8 + s3 * 4) * 4u;

    const __half* kg  = g_kth + base;            // [s][d]
    const __half* vtg = g_vth + base;            // [d][s]

    load_kv_tile(kg, vtg, k_u32, v_u32, tid);

    // ---- Q: load, scale(+log2e), pack to half2 a-frags ----
    uint32_t qreg[8][4];
    {
        const float* qp = q + base;
        const long r0 = wrow + g, r1 = r0 + 8;
        #pragma unroll
        for (int ks = 0; ks < 8; ++ks) {
            int col = ks * 16 + 2 * c;
            qreg[ks][0] = pack2(qp[r0 * D_ + col]     * scale, qp[r0 * D_ + col + 1] * scale);
            qreg[ks][1] = pack2(qp[r1 * D_ + col]     * scale, qp[r1 * D_ + col + 1] * scale);
            qreg[ks][2] = pack2(qp[r0 * D_ + col + 8] * scale, qp[r0 * D_ + col + 9] * scale);
            qreg[ks][3] = pack2(qp[r1 * D_ + col + 8] * scale, qp[r1 * D_ + col + 9] * scale);
        }
    }

    float oacc[16][4];
    #pragma unroll
    for (int nt = 0; nt < 16; ++nt)
        oacc[nt][0] = oacc[nt][1] = oacc[nt][2] = oacc[nt][3] = 0.f;
    float m0 = -1e30f, m1 = -1e30f, l0 = 0.f, l1 = 0.f;

    for (int j = 0; j < njt; ++j) {
        const int st = j & 1;
        if (j + 1 < njt) {
            const int ns = (j + 1) & 1;
            load_kv_tile(kg + (long)(j + 1) * BC * D_,
                         vtg + (j + 1) * BC,
                         k_u32 + (uint32_t)(ns * KTILE_W) * 4u,
                         v_u32 + (uint32_t)(ns * VTILE_W) * 4u, tid);
            asm volatile("cp.async.wait_group 1;");
        } else {
            asm volatile("cp.async.wait_group 0;");
        }
        __syncthreads();

        const int kvb = j * BC;

        // Skip warp-tiles entirely above the diagonal (fully masked).
        if (wrow + 15 >= kvb) {
            const uint32_t ktb = k_u32 + (uint32_t)(st * KTILE_W) * 4u + koff;
            const uint32_t vtb = v_u32 + (uint32_t)(st * VTILE_W) * 4u + voff;

            // ---- S = Q K^T (16x64 per warp) ----
            float sacc[8][4];
            #pragma unroll
            for (int nt = 0; nt < 8; ++nt)
                sacc[nt][0] = sacc[nt][1] = sacc[nt][2] = sacc[nt][3] = 0.f;

            #pragma unroll
            for (int nt = 0; nt < 8; ++nt) {
                const uint32_t krow = ktb + (uint32_t)(nt * 8 * KSTW) * 4u;
                #pragma unroll
                for (int kp = 0; kp < 4; ++kp) {
                    uint32_t b0, b1, b2, b3;
                    ldsm4(b0, b1, b2, b3, krow + (uint32_t)(kp * 16) * 4u);
                    mma_f16(sacc[nt], qreg[2*kp][0], qreg[2*kp][1], qreg[2*kp][2], qreg[2*kp][3], b0, b1);
                    mma_f16(sacc[nt], qreg[2*kp+1][0], qreg[2*kp+1][1], qreg[2*kp+1][2], qreg[2*kp+1][3], b2, b3);
                }
            }

            // ---- causal mask (near-diagonal tiles only) ----
            if (kvb + BC - 1 > wrow) {
                #pragma unroll
                for (int nt = 0; nt < 8; ++nt) {
                    #pragma unroll
                    for (int idx = 0; idx < 4; ++idx) {
                        int col = kvb + nt * 8 + (c << 1) + (idx & 1);
                        int row = wrow + g + ((idx >> 1) << 3);
                        if (col > row) sacc[nt][idx] = -1e30f;
                    }
                }
            }

            // ---- online softmax (base 2), rows g and g+8 ----
            float tm0 = -1e30f, tm1 = -1e30f;
            #pragma unroll
            for (int nt = 0; nt < 8; ++nt) {
                tm0 = fmaxf(tm0, fmaxf(sacc[nt][0], sacc[nt][1]));
                tm1 = fmaxf(tm1, fmaxf(sacc[nt][2], sacc[nt][3]));
            }
            tm0 = fmaxf(tm0, __shfl_xor_sync(0xffffffffu, tm0, 1));
            tm0 = fmaxf(tm0, __shfl_xor_sync(0xffffffffu, tm0, 2));
            tm1 = fmaxf(tm1, __shfl_xor_sync(0xffffffffu, tm1, 1));
            tm1 = fmaxf(tm1, __shfl_xor_sync(0xffffffffu, tm1, 2));

            const float nm0 = fmaxf(m0, tm0), nm1 = fmaxf(m1, tm1);
            const float a0 = ex2(m0 - nm0), a1 = ex2(m1 - nm1);
            m0 = nm0; m1 = nm1;

            // ---- exp + pack P directly into PV A-fragments (no smem!) ----
            // A-frag of P 16x16 block kb: a0=(g, 2c|tile 2kb), a1=(g+8, same),
            // a2=(g, 2c|tile 2kb+1), a3=(g+8, same)  ==  S C-frag pairs.
            uint32_t pa[4][4];
            float ts0 = 0.f, ts1 = 0.f;
            #pragma unroll
            for (int nt = 0; nt < 8; ++nt) {
                float p00 = ex2(sacc[nt][0] - nm0);
                float p01 = ex2(sacc[nt][1] - nm0);
                float p10 = ex2(sacc[nt][2] - nm1);
                float p11 = ex2(sacc[nt][3] - nm1);
                ts0 += p00 + p01;
                ts1 += p10 + p11;
                if ((nt & 1) == 0) {
                    pa[nt >> 1][0] = pack2(p00, p01);
                    pa[nt >> 1][1] = pack2(p10, p11);
                } else {
                    pa[nt >> 1][2] = pack2(p00, p01);
                    pa[nt >> 1][3] = pack2(p10, p11);
                }
            }
            ts0 += __shfl_xor_sync(0xffffffffu, ts0, 1);
            ts0 += __shfl_xor_sync(0xffffffffu, ts0, 2);
            ts1 += __shfl_xor_sync(0xffffffffu, ts1, 1);
            ts1 += __shfl_xor_sync(0xffffffffu, ts1, 2);
            l0 = l0 * a0 + ts0;
            l1 = l1 * a1 + ts1;

            #pragma unroll
            for (int nt = 0; nt < 16; ++nt) {
                oacc[nt][0] *= a0; oacc[nt][1] *= a0;
                oacc[nt][2] *= a1; oacc[nt][3] *= a1;
            }

            // ---- O += P V (16x128 per warp) ----
            #pragma unroll
            for (int nt = 0; nt < 16; ++nt) {
                const uint32_t vrow = vtb + (uint32_t)(nt * 8 * VSTW) * 4u;
                uint32_t b0, b1, b2, b3, b4, b5, b6, b7;
                ldsm4(b0, b1, b2, b3, vrow);
                ldsm4(b4, b5, b6, b7, vrow + 64u);
                mma_f16(oacc[nt], pa[0][0], pa[0][1], pa[0][2], pa[0][3], b0, b1);
                mma_f16(oacc[nt], pa[1][0], pa[1][1], pa[1][2], pa[1][3], b2, b3);
                mma_f16(oacc[nt], pa[2][0], pa[2][1], pa[2][2], pa[2][3], b4, b5);
                mma_f16(oacc[nt], pa[3][0], pa[3][1], pa[3][2], pa[3][3], b6, b7);
            }
        }

        __syncthreads();  // all warps done with this stage before refill
    }

    // ---- epilogue: normalize and store ----
    const float inv0 = 1.f / l0, inv1 = 1.f / l1;
    float* op = out + base;
    const long r0 = wrow + g, r1 = r0 + 8;
    #pragma unroll
    for (int nt = 0; nt < 16; ++nt) {
        int col = nt * 8 + (c << 1);
        float2 o0 = make_float2(oacc[nt][0] * inv0, oacc[nt][1] * inv0);
        float2 o1 = make_float2(oacc[nt][2] * inv1, oacc[nt][3] * inv1);
        *(float2*)(op + r0 * D_ + col) = o0;
        *(float2*)(op + r1 * D_ + col) = o1;
    }
}

extern "C" void kernel_launch(void* const* d_in, const int* in_sizes, int n_in,
                              void* d_out, int out_size) {
    const float* q = (const float*)d_in[0];
    const float* k = (const float*)d_in[1];
    const float* v = (const float*)d_in[2];
    float* out = (float*)d_out;

    dim3 pgrid(S_ / 64, D_ / 64, B_ * H_);
    prep_kv_kernel<<<pgrid, 256>>>(v, (const float4*)k);

    cudaFuncSetAttribute(fa_regp_kernel,
                         cudaFuncAttributeMaxDynamicSharedMemorySize, SMEM_BYTES);
    dim3 grid(S_ / BR, B_ * H_);
    fa_regp_kernel<<<grid, THREADS, SMEM_BYTES>>>(q, out);
}

// round 12
// speedup vs baseline: 1.1151x; 1.1151x over previous
#include <cuda_runtime.h>
#include <cuda_fp16.h>
#include <cstdint>

// Causal SDPA: B=2, H=16, S=2048, D=128, fp32 in/out.
// R12: software pipelining. QK(j+1) MMAs are issued in the same block as
// softmax(j) so the tensor pipe works through the scalar phase.
//   - two S accumulators (sacc/snxt), register copy at iteration end
//   - 3-stage smem ring: V(j) + K(j+1) consumed while tile j+2 loads
//   - P in registers (S C-frags == PV A-frags), base-2 ex2 softmax
//   - fp16 m16n8k16 mma w/ f32 accum, ldmatrix, fused fp16 prologue

#define B_ 2
#define H_ 16
#define S_ 2048
#define D_ 128

constexpr int BR      = 64;
constexpr int BC      = 64;
constexpr int THREADS = 128;
constexpr int STAGES  = 3;

// smem row strides in 32-bit words; stride % 32 == 4 -> ldmatrix phases
// cover all 32 banks (conflict-free).
constexpr int KSTW = 68;   // K tile row: 128 halfs + pad
constexpr int VSTW = 36;   // VT tile row: 64 halfs + pad

constexpr int KTILE_W = BC * KSTW;               // 4352 words / stage
constexpr int VTILE_W = D_ * VSTW;               // 4608 words / stage
constexpr int SM_V    = STAGES * KTILE_W;        // 13056
constexpr int SMEM_WORDS = STAGES * (KTILE_W + VTILE_W);  // 26880
constexpr int SMEM_BYTES = SMEM_WORDS * 4;       // 107520 B -> 2 CTAs/SM

constexpr int KV_ELEMS = B_ * H_ * S_ * D_;

__device__ __align__(16) __half g_kth[KV_ELEMS];   // K fp16 [bh][s][d]
__device__ __align__(16) __half g_vth[KV_ELEMS];   // V fp16 transposed [bh][d][s]

// ---------------------------------------------------------------------------
// Fused prologue (unchanged): V->fp16 transposed tile + K->fp16 slice.
// ---------------------------------------------------------------------------
__global__ void __launch_bounds__(256)
prep_kv_kernel(const float* __restrict__ v, const float4* __restrict__ k) {
    __shared__ __half tile[64][65];
    const int bh = blockIdx.z;
    const int s0 = blockIdx.x * 64;
    const int d0 = blockIdx.y * 64;
    const float* vp = v + (long)bh * S_ * D_;
    __half* vtp = g_vth + (long)bh * (long)D_ * S_;

    const int tx = threadIdx.x & 15;
    const int ty = threadIdx.x >> 4;
    #pragma unroll
    for (int p = 0; p < 4; ++p) {
        int si = ty + p * 16;
        float4 a = *(const float4*)(vp + (long)(s0 + si) * D_ + d0 + tx * 4);
        tile[si][tx * 4 + 0] = __float2half_rn(a.x);
        tile[si][tx * 4 + 1] = __float2half_rn(a.y);
        tile[si][tx * 4 + 2] = __float2half_rn(a.z);
        tile[si][tx * 4 + 3] = __float2half_rn(a.w);
    }
    {
        const long nblk = (long)gridDim.x * gridDim.y * gridDim.z;
        const long bid  = (long)(blockIdx.z * gridDim.y + blockIdx.y) * gridDim.x
                        + blockIdx.x;
        const long per  = (KV_ELEMS / 4) / nblk;
        uint2* kd = reinterpret_cast<uint2*>(g_kth);
        long i0 = bid * per;
        for (long i = i0 + threadIdx.x; i < i0 + per; i += 256) {
            float4 a = k[i];
            __half2 lo = __floats2half2_rn(a.x, a.y);
            __half2 hi = __floats2half2_rn(a.z, a.w);
            uint2 o;
            o.x = *(uint32_t*)&lo;
            o.y = *(uint32_t*)&hi;
            kd[i] = o;
        }
    }
    __syncthreads();
    const int lane = threadIdx.x & 31;
    const int w    = threadIdx.x >> 5;
    #pragma unroll
    for (int p = 0; p < 8; ++p) {
        int di = w + p * 8;
        __half2 h = __halves2half2(tile[2 * lane][di], tile[2 * lane + 1][di]);
        *(__half2*)(vtp + (long)(d0 + di) * S_ + s0 + 2 * lane) = h;
    }
}

// ---------------------------------------------------------------------------
__device__ __forceinline__ void mma_f16(float c[4],
                                        uint32_t a0, uint32_t a1, uint32_t a2, uint32_t a3,
                                        uint32_t b0, uint32_t b1) {
    asm volatile(
        "mma.sync.aligned.m16n8k16.row.col.f32.f16.f16.f32 "
        "{%0,%1,%2,%3}, {%4,%5,%6,%7}, {%8,%9}, {%0,%1,%2,%3};"
        : "+f"(c[0]), "+f"(c[1]), "+f"(c[2]), "+f"(c[3])
        : "r"(a0), "r"(a1), "r"(a2), "r"(a3), "r"(b0), "r"(b1));
}
__device__ __forceinline__ void ldsm4(uint32_t& r0, uint32_t& r1,
                                      uint32_t& r2, uint32_t& r3, uint32_t addr) {
    asm volatile("ldmatrix.sync.aligned.m8n8.x4.shared.b16 {%0,%1,%2,%3}, [%4];"
                 : "=r"(r0), "=r"(r1), "=r"(r2), "=r"(r3) : "r"(addr));
}
__device__ __forceinline__ void cp_async16(uint32_t dst, const void* src) {
    asm volatile("cp.async.cg.shared.global [%0], [%1], 16;" :: "r"(dst), "l"(src));
}
__device__ __forceinline__ uint32_t pack2(float a, float b) {
    __half2 h = __floats2half2_rn(a, b);
    return *(uint32_t*)&h;
}
__device__ __forceinline__ float ex2(float x) {
    float r;
    asm("ex2.approx.ftz.f32 %0, %1;" : "=f"(r) : "f"(x));
    return r;
}

// Load one K tile (BC x 128 halfs) + one VT tile (128 x BC halfs); 1 group.
__device__ __forceinline__ void load_kv_tile(const __half* kg, const __half* vtg,
                                             uint32_t kdst, uint32_t vdst, int tid) {
    #pragma unroll
    for (int it = 0; it < (BC * 16) / THREADS; ++it) {
        int i = tid + it * THREADS;
        int row = i >> 4, ch = i & 15;
        cp_async16(kdst + (uint32_t)(row * KSTW + ch * 4) * 4u, kg + row * D_ + ch * 8);
    }
    #pragma unroll
    for (int it = 0; it < (D_ * 8) / THREADS; ++it) {
        int i = tid + it * THREADS;
        int row = i >> 3, ch = i & 7;
        cp_async16(vdst + (uint32_t)(row * VSTW + ch * 4) * 4u, vtg + (long)row * S_ + ch * 8);
    }
    asm volatile("cp.async.commit_group;");
}

// S = Q K^T for one 16x64 warp-tile (zero-init + 32 LDSM + 64 MMA).
__device__ __forceinline__ void qk_block(float sacc[8][4],
                                         const uint32_t qreg[8][4], uint32_t ktb) {
    #pragma unroll
    for (int nt = 0; nt < 8; ++nt)
        sacc[nt][0] = sacc[nt][1] = sacc[nt][2] = sacc[nt][3] = 0.f;
    #pragma unroll
    for (int nt = 0; nt < 8; ++nt) {
        const uint32_t krow = ktb + (uint32_t)(nt * 8 * KSTW) * 4u;
        #pragma unroll
        for (int kp = 0; kp < 4; ++kp) {
            uint32_t b0, b1, b2, b3;
            ldsm4(b0, b1, b2, b3, krow + (uint32_t)(kp * 16) * 4u);
            mma_f16(sacc[nt], qreg[2*kp][0], qreg[2*kp][1], qreg[2*kp][2], qreg[2*kp][3], b0, b1);
            mma_f16(sacc[nt], qreg[2*kp+1][0], qreg[2*kp+1][1], qreg[2*kp+1][2], qreg[2*kp+1][3], b2, b3);
        }
    }
}

__global__ void __launch_bounds__(THREADS, 2)
fa_pipe_kernel(const float* __restrict__ q, float* __restrict__ out) {
    extern __shared__ __align__(16) uint32_t smem[];

    const int tid  = threadIdx.x;
    const int w    = tid >> 5;
    const int lane = tid & 31;
    const int g    = lane >> 2;
    const int c    = lane & 3;
    const int r8   = lane & 7;
    const int s3   = (lane >> 3) & 1;
    const int s4   = lane >> 4;

    const int qt     = (int)(gridDim.x - 1) - (int)blockIdx.x;  // longest first
    const int bh     = blockIdx.y;
    const long base  = (long)bh * S_ * D_;
    const int q_base = qt * BR;
    const int njt    = qt + 1;
    const int wrow   = q_base + w * 16;

    // D^-0.5 * log2(e): softmax in base 2 (ex2 = single MUFU op)
    const float scale = 0.08838834764831845f * 1.4426950408889634f;

    const uint32_t smem_u32 = (uint32_t)__cvta_generic_to_shared(smem);
    const uint32_t k_u32    = smem_u32;
    const uint32_t v_u32    = smem_u32 + (uint32_t)SM_V * 4u;

    const uint32_t koff = (uint32_t)(r8 * KSTW + s4 * 8 + s3 * 4) * 4u;
    const uint32_t voff = (uint32_t)(r8 * VSTW + s4 * 8 + s3 * 4) * 4u;

    const __half* kg  = g_kth + base;    // [s][d]
    const __half* vtg = g_vth + base;    // [d][s]

    // ---- prologue loads: tile 0 (stage 0), tile 1 (stage 1) ----
    load_kv_tile(kg, vtg, k_u32, v_u32, tid);
    if (njt > 1)
        load_kv_tile(kg + BC * D_, vtg + BC,
                     k_u32 + (uint32_t)KTILE_W * 4u, v_u32 + (uint32_t)VTILE_W * 4u, tid);

    // ---- Q: load, scale(+log2e), pack to half2 a-frags ----
    uint32_t qreg[8][4];
    {
        const float* qp = q + base;
        const long r0 = wrow + g, r1 = r0 + 8;
        #pragma unroll
        for (int ks = 0; ks < 8; ++ks) {
            int col = ks * 16 + 2 * c;
            qreg[ks][0] = pack2(qp[r0 * D_ + col]     * scale, qp[r0 * D_ + col + 1] * scale);
            qreg[ks][1] = pack2(qp[r1 * D_ + col]     * scale, qp[r1 * D_ + col + 1] * scale);
            qreg[ks][2] = pack2(qp[r0 * D_ + col + 8] * scale, qp[r0 * D_ + col + 9] * scale);
            qreg[ks][3] = pack2(qp[r1 * D_ + col + 8] * scale, qp[r1 * D_ + col + 9] * scale);
        }
    }

    float oacc[16][4];
    #pragma unroll
    for (int nt = 0; nt < 16; ++nt)
        oacc[nt][0] = oacc[nt][1] = oacc[nt][2] = oacc[nt][3] = 0.f;
    float m0 = -1e30f, m1 = -1e30f, l0 = 0.f, l1 = 0.f;

    // ---- wait tile 0, then compute S(0) ----
    if (njt > 1) { asm volatile("cp.async.wait_group 1;"); }
    else         { asm volatile("cp.async.wait_group 0;"); }
    __syncthreads();

    float sacc[8][4], snxt[8][4];
    qk_block(sacc, qreg, k_u32 + koff);   // tile 0, stage 0

    int s_cur = 0, s_nxt = 1, s_pre = 2;

    for (int j = 0; j < njt; ++j) {
        const bool has_next = (j + 1 < njt);

        // issue loads for tile j+2 into s_pre (stage freed by iter j-1)
        bool issued = false;
        if (j + 2 < njt) {
            load_kv_tile(kg + (long)(j + 2) * BC * D_, vtg + (j + 2) * BC,
                         k_u32 + (uint32_t)(s_pre * KTILE_W) * 4u,
                         v_u32 + (uint32_t)(s_pre * VTILE_W) * 4u, tid);
            issued = true;
        }
        if (issued) { asm volatile("cp.async.wait_group 1;"); }
        else        { asm volatile("cp.async.wait_group 0;"); }
        __syncthreads();   // publish tile j+1 to all warps

        const int kvb = j * BC;

        // ---- QK(j+1): independent MMAs issued alongside softmax(j) ----
        if (has_next)
            qk_block(snxt, qreg, k_u32 + (uint32_t)(s_nxt * KTILE_W) * 4u + koff);

        // ---- causal mask on tile j (near-diagonal only) ----
        if (kvb + BC - 1 > wrow) {
            #pragma unroll
            for (int nt = 0; nt < 8; ++nt) {
                #pragma unroll
                for (int idx = 0; idx < 4; ++idx) {
                    int col = kvb + nt * 8 + (c << 1) + (idx & 1);
                    int row = wrow + g + ((idx >> 1) << 3);
                    if (col > row) sacc[nt][idx] = -1e30f;
                }
            }
        }

        // ---- online softmax (base 2), rows g and g+8 ----
        float tm0 = -1e30f, tm1 = -1e30f;
        #pragma unroll
        for (int nt = 0; nt < 8; ++nt) {
            tm0 = fmaxf(tm0, fmaxf(sacc[nt][0], sacc[nt][1]));
            tm1 = fmaxf(tm1, fmaxf(sacc[nt][2], sacc[nt][3]));
        }
        tm0 = fmaxf(tm0, __shfl_xor_sync(0xffffffffu, tm0, 1));
        tm0 = fmaxf(tm0, __shfl_xor_sync(0xffffffffu, tm0, 2));
        tm1 = fmaxf(tm1, __shfl_xor_sync(0xffffffffu, tm1, 1));
        tm1 = fmaxf(tm1, __shfl_xor_sync(0xffffffffu, tm1, 2));

        const float nm0 = fmaxf(m0, tm0), nm1 = fmaxf(m1, tm1);
        const float a0 = ex2(m0 - nm0), a1 = ex2(m1 - nm1);
        m0 = nm0; m1 = nm1;

        // ---- exp + pack P directly into PV A-fragments ----
        uint32_t pa[4][4];
        float ts0 = 0.f, ts1 = 0.f;
        #pragma unroll
        for (int nt = 0; nt < 8; ++nt) {
            float p00 = ex2(sacc[nt][0] - nm0);
            float p01 = ex2(sacc[nt][1] - nm0);
            float p10 = ex2(sacc[nt][2] - nm1);
            float p11 = ex2(sacc[nt][3] - nm1);
            ts0 += p00 + p01;
            ts1 += p10 + p11;
            if ((nt & 1) == 0) {
                pa[nt >> 1][0] = pack2(p00, p01);
                pa[nt >> 1][1] = pack2(p10, p11);
            } else {
                pa[nt >> 1][2] = pack2(p00, p01);
                pa[nt >> 1][3] = pack2(p10, p11);
            }
        }
        ts0 += __shfl_xor_sync(0xffffffffu, ts0, 1);
        ts0 += __shfl_xor_sync(0xffffffffu, ts0, 2);
        ts1 += __shfl_xor_sync(0xffffffffu, ts1, 1);
        ts1 += __shfl_xor_sync(0xffffffffu, ts1, 2);
        l0 = l0 * a0 + ts0;
        l1 = l1 * a1 + ts1;

        #pragma unroll
        for (int nt = 0; nt < 16; ++nt) {
            oacc[nt][0] *= a0; oacc[nt][1] *= a0;
            oacc[nt][2] *= a1; oacc[nt][3] *= a1;
        }

        // ---- O += P V (V stage s_cur) ----
        const uint32_t vtb = v_u32 + (uint32_t)(s_cur * VTILE_W) * 4u + voff;
        #pragma unroll
        for (int nt = 0; nt < 16; ++nt) {
            const uint32_t vrow = vtb + (uint32_t)(nt * 8 * VSTW) * 4u;
            uint32_t b0, b1, b2, b3, b4, b5, b6, b7;
            ldsm4(b0, b1, b2, b3, vrow);
            ldsm4(b4, b5, b6, b7, vrow + 64u);
            mma_f16(oacc[nt], pa[0][0], pa[0][1], pa[0][2], pa[0][3], b0, b1);
            mma_f16(oacc[nt], pa[1][0], pa[1][1], pa[1][2], pa[1][3], b2, b3);
            mma_f16(oacc[nt], pa[2][0], pa[2][1], pa[2][2], pa[2][3], b4, b5);
            mma_f16(oacc[nt], pa[3][0], pa[3][1], pa[3][2], pa[3][3], b6, b7);
        }

        // ---- roll S accumulator and stage ring ----
        if (has_next) {
            #pragma unroll
            for (int nt = 0; nt < 8; ++nt) {
                sacc[nt][0] = snxt[nt][0]; sacc[nt][1] = snxt[nt][1];
                sacc[nt][2] = snxt[nt][2]; sacc[nt][3] = snxt[nt][3];
            }
        }
        __syncthreads();   // all warps done with stage s_cur before refill

        const int t = s_cur; s_cur = s_nxt; s_nxt = s_pre; s_pre = t;
    }

    // ---- epilogue: normalize and store ----
    const float inv0 = 1.f / l0, inv1 = 1.f / l1;
    float* op = out + base;
    const long r0 = wrow + g, r1 = r0 + 8;
    #pragma unroll
    for (int nt = 0; nt < 16; ++nt) {
        int col = nt * 8 + (c << 1);
        float2 o0 = make_float2(oacc[nt][0] * inv0, oacc[nt][1] * inv0);
        float2 o1 = make_float2(oacc[nt][2] * inv1, oacc[nt][3] * inv1);
        *(float2*)(op + r0 * D_ + col) = o0;
        *(float2*)(op + r1 * D_ + col) = o1;
    }
}

extern "C" void kernel_launch(void* const* d_in, const int* in_sizes, int n_in,
                              void* d_out, int out_size) {
    const float* q = (const float*)d_in[0];
    const float* k = (const float*)d_in[1];
    const float* v = (const float*)d_in[2];
    float* out = (float*)d_out;

    dim3 pgrid(S_ / 64, D_ / 64, B_ * H_);
    prep_kv_kernel<<<pgrid, 256>>>(v, (const float4*)k);

    cudaFuncSetAttribute(fa_pipe_kernel,
                         cudaFuncAttributeMaxDynamicSharedMemorySize, SMEM_BYTES);
    dim3 grid(S_ / BR, B_ * H_);
    fa_pipe_kernel<<<grid, THREADS, SMEM_BYTES>>>(q, out);
}

// round 13
// speedup vs baseline: 1.1478x; 1.0293x over previous
#include <cuda_runtime.h>
#include <cuda_fp16.h>
#include <cstdint>

// Causal SDPA: B=2, H=16, S=2048, D=128, fp32 in/out.
// R13: fully skewed software pipeline. Each iteration executes
//   PV(j)  +  QK(j+2)  +  softmax(j+1)
// in one block so every scalar chain overlaps an MMA burst.
//   - O rescale deferred to just before PV (telescoping preserved)
//   - K ring 3 stages (consumed 2 ahead), V ring 2 stages (consumed in-iter)
//   - P in registers (S C-frags == PV A-frags), base-2 ex2 softmax
//   - fp16 m16n8k16 mma w/ f32 accum, ldmatrix, fused fp16 prologue

#define B_ 2
#define H_ 16
#define S_ 2048
#define D_ 128

constexpr int BR      = 64;
constexpr int BC      = 64;
constexpr int THREADS = 128;

// smem row strides in 32-bit words; stride % 32 == 4 -> ldmatrix phases
// cover all 32 banks (conflict-free). Stage strides are %32==0 (preserved).
constexpr int KSTW = 68;   // K tile row: 128 halfs + pad
constexpr int VSTW = 36;   // VT tile row: 64 halfs + pad

constexpr int KTILE_W = BC * KSTW;               // 4352 words / stage
constexpr int VTILE_W = D_ * VSTW;               // 4608 words / stage
constexpr int KSTAGES = 3;
constexpr int VSTAGES = 2;
constexpr int SM_V    = KSTAGES * KTILE_W;       // 13056
constexpr int SMEM_WORDS = KSTAGES * KTILE_W + VSTAGES * VTILE_W;  // 22272
constexpr int SMEM_BYTES = SMEM_WORDS * 4;       // 89088 B -> 2 CTAs/SM

constexpr int KV_ELEMS = B_ * H_ * S_ * D_;

__device__ __align__(16) __half g_kth[KV_ELEMS];   // K fp16 [bh][s][d]
__device__ __align__(16) __half g_vth[KV_ELEMS];   // V fp16 transposed [bh][d][s]

// ---------------------------------------------------------------------------
// Fused prologue (unchanged): V->fp16 transposed tile + K->fp16 slice.
// ---------------------------------------------------------------------------
__global__ void __launch_bounds__(256)
prep_kv_kernel(const float* __restrict__ v, const float4* __restrict__ k) {
    __shared__ __half tile[64][65];
    const int bh = blockIdx.z;
    const int s0 = blockIdx.x * 64;
    const int d0 = blockIdx.y * 64;
    const float* vp = v + (long)bh * S_ * D_;
    __half* vtp = g_vth + (long)bh * (long)D_ * S_;

    const int tx = threadIdx.x & 15;
    const int ty = threadIdx.x >> 4;
    #pragma unroll
    for (int p = 0; p < 4; ++p) {
        int si = ty + p * 16;
        float4 a = *(const float4*)(vp + (long)(s0 + si) * D_ + d0 + tx * 4);
        tile[si][tx * 4 + 0] = __float2half_rn(a.x);
        tile[si][tx * 4 + 1] = __float2half_rn(a.y);
        tile[si][tx * 4 + 2] = __float2half_rn(a.z);
        tile[si][tx * 4 + 3] = __float2half_rn(a.w);
    }
    {
        const long nblk = (long)gridDim.x * gridDim.y * gridDim.z;
        const long bid  = (long)(blockIdx.z * gridDim.y + blockIdx.y) * gridDim.x
                        + blockIdx.x;
        const long per  = (KV_ELEMS / 4) / nblk;
        uint2* kd = reinterpret_cast<uint2*>(g_kth);
        long i0 = bid * per;
        for (long i = i0 + threadIdx.x; i < i0 + per; i += 256) {
            float4 a = k[i];
            __half2 lo = __floats2half2_rn(a.x, a.y);
            __half2 hi = __floats2half2_rn(a.z, a.w);
            uint2 o;
            o.x = *(uint32_t*)&lo;
            o.y = *(uint32_t*)&hi;
            kd[i] = o;
        }
    }
    __syncthreads();
    const int lane = threadIdx.x & 31;
    const int w    = threadIdx.x >> 5;
    #pragma unroll
    for (int p = 0; p < 8; ++p) {
        int di = w + p * 8;
        __half2 h = __halves2half2(tile[2 * lane][di], tile[2 * lane + 1][di]);
        *(__half2*)(vtp + (long)(d0 + di) * S_ + s0 + 2 * lane) = h;
    }
}

// ---------------------------------------------------------------------------
__device__ __forceinline__ void mma_f16(float c[4],
                                        uint32_t a0, uint32_t a1, uint32_t a2, uint32_t a3,
                                        uint32_t b0, uint32_t b1) {
    asm volatile(
        "mma.sync.aligned.m16n8k16.row.col.f32.f16.f16.f32 "
        "{%0,%1,%2,%3}, {%4,%5,%6,%7}, {%8,%9}, {%0,%1,%2,%3};"
        : "+f"(c[0]), "+f"(c[1]), "+f"(c[2]), "+f"(c[3])
        : "r"(a0), "r"(a1), "r"(a2), "r"(a3), "r"(b0), "r"(b1));
}
__device__ __forceinline__ void ldsm4(uint32_t& r0, uint32_t& r1,
                                      uint32_t& r2, uint32_t& r3, uint32_t addr) {
    asm volatile("ldmatrix.sync.aligned.m8n8.x4.shared.b16 {%0,%1,%2,%3}, [%4];"
                 : "=r"(r0), "=r"(r1), "=r"(r2), "=r"(r3) : "r"(addr));
}
__device__ __forceinline__ void cp_async16(uint32_t dst, const void* src) {
    asm volatile("cp.async.cg.shared.global [%0], [%1], 16;" :: "r"(dst), "l"(src));
}
__device__ __forceinline__ uint32_t pack2(float a, float b) {
    __half2 h = __floats2half2_rn(a, b);
    return *(uint32_t*)&h;
}
__device__ __forceinline__ float ex2(float x) {
    float r;
    asm("ex2.approx.ftz.f32 %0, %1;" : "=f"(r) : "f"(x));
    return r;
}

__device__ __forceinline__ void load_k_tile(const __half* kg, uint32_t kdst, int tid) {
    #pragma unroll
    for (int it = 0; it < (BC * 16) / THREADS; ++it) {
        int i = tid + it * THREADS;
        int row = i >> 4, ch = i & 15;
        cp_async16(kdst + (uint32_t)(row * KSTW + ch * 4) * 4u, kg + row * D_ + ch * 8);
    }
}
__device__ __forceinline__ void load_v_tile(const __half* vtg, uint32_t vdst, int tid) {
    #pragma unroll
    for (int it = 0; it < (D_ * 8) / THREADS; ++it) {
        int i = tid + it * THREADS;
        int row = i >> 3, ch = i & 7;
        cp_async16(vdst + (uint32_t)(row * VSTW + ch * 4) * 4u, vtg + (long)row * S_ + ch * 8);
    }
}
#define COMMIT() asm volatile("cp.async.commit_group;")
#define WAIT1()  asm volatile("cp.async.wait_group 1;")

// S = Q K^T for one 16x64 warp-tile (zero-init + 32 LDSM + 64 MMA).
__device__ __forceinline__ void qk_block(float sacc[8][4],
                                         const uint32_t qreg[8][4], uint32_t ktb) {
    #pragma unroll
    for (int nt = 0; nt < 8; ++nt)
        sacc[nt][0] = sacc[nt][1] = sacc[nt][2] = sacc[nt][3] = 0.f;
    #pragma unroll
    for (int nt = 0; nt < 8; ++nt) {
        const uint32_t krow = ktb + (uint32_t)(nt * 8 * KSTW) * 4u;
        #pragma unroll
        for (int kp = 0; kp < 4; ++kp) {
            uint32_t b0, b1, b2, b3;
            ldsm4(b0, b1, b2, b3, krow + (uint32_t)(kp * 16) * 4u);
            mma_f16(sacc[nt], qreg[2*kp][0], qreg[2*kp][1], qreg[2*kp][2], qreg[2*kp][3], b0, b1);
            mma_f16(sacc[nt], qreg[2*kp+1][0], qreg[2*kp+1][1], qreg[2*kp+1][2], qreg[2*kp+1][3], b2, b3);
        }
    }
}

// mask + online softmax for one tile held in s[8][4]; produces P a-frags.
__device__ __forceinline__ void softmax_tile(float s[8][4], int kvb, int wrow,
                                             int g, int c,
                                             float& m0, float& m1,
                                             float& l0, float& l1,
                                             float& a0, float& a1,
                                             uint32_t pa[4][4]) {
    if (kvb + BC - 1 > wrow) {
        #pragma unroll
        for (int nt = 0; nt < 8; ++nt) {
            #pragma unroll
            for (int idx = 0; idx < 4; ++idx) {
                int col = kvb + nt * 8 + (c << 1) + (idx & 1);
                int row = wrow + g + ((idx >> 1) << 3);
                if (col > row) s[nt][idx] = -1e30f;
            }
        }
    }
    float tm0 = -1e30f, tm1 = -1e30f;
    #pragma unroll
    for (int nt = 0; nt < 8; ++nt) {
        tm0 = fmaxf(tm0, fmaxf(s[nt][0], s[nt][1]));
        tm1 = fmaxf(tm1, fmaxf(s[nt][2], s[nt][3]));
    }
    tm0 = fmaxf(tm0, __shfl_xor_sync(0xffffffffu, tm0, 1));
    tm0 = fmaxf(tm0, __shfl_xor_sync(0xffffffffu, tm0, 2));
    tm1 = fmaxf(tm1, __shfl_xor_sync(0xffffffffu, tm1, 1));
    tm1 = fmaxf(tm1, __shfl_xor_sync(0xffffffffu, tm1, 2));

    const float nm0 = fmaxf(m0, tm0), nm1 = fmaxf(m1, tm1);
    a0 = ex2(m0 - nm0); a1 = ex2(m1 - nm1);
    m0 = nm0; m1 = nm1;

    float ts0 = 0.f, ts1 = 0.f;
    #pragma unroll
    for (int nt = 0; nt < 8; ++nt) {
        float p00 = ex2(s[nt][0] - nm0);
        float p01 = ex2(s[nt][1] - nm0);
        float p10 = ex2(s[nt][2] - nm1);
        float p11 = ex2(s[nt][3] - nm1);
        ts0 += p00 + p01;
        ts1 += p10 + p11;
        if ((nt & 1) == 0) {
            pa[nt >> 1][0] = pack2(p00, p01);
            pa[nt >> 1][1] = pack2(p10, p11);
        } else {
            pa[nt >> 1][2] = pack2(p00, p01);
            pa[nt >> 1][3] = pack2(p10, p11);
        }
    }
    ts0 += __shfl_xor_sync(0xffffffffu, ts0, 1);
    ts0 += __shfl_xor_sync(0xffffffffu, ts0, 2);
    ts1 += __shfl_xor_sync(0xffffffffu, ts1, 1);
    ts1 += __shfl_xor_sync(0xffffffffu, ts1, 2);
    l0 = l0 * a0 + ts0;
    l1 = l1 * a1 + ts1;
}

__global__ void __launch_bounds__(THREADS, 2)
fa_skew_kernel(const float* __restrict__ q, float* __restrict__ out) {
    extern __shared__ __align__(16) uint32_t smem[];

    const int tid  = threadIdx.x;
    const int w    = tid >> 5;
    const int lane = tid & 31;
    const int g    = lane >> 2;
    const int c    = lane & 3;
    const int r8   = lane & 7;
    const int s3   = (lane >> 3) & 1;
    const int s4   = lane >> 4;

    const int qt     = (int)(gridDim.x - 1) - (int)blockIdx.x;  // longest first
    const int bh     = blockIdx.y;
    const long base  = (long)bh * S_ * D_;
    const int q_base = qt * BR;
    const int njt    = qt + 1;
    const int wrow   = q_base + w * 16;

    // D^-0.5 * log2(e): softmax in base 2
    const float scale = 0.08838834764831845f * 1.4426950408889634f;

    const uint32_t smem_u32 = (uint32_t)__cvta_generic_to_shared(smem);
    const uint32_t k_u32    = smem_u32;
    const uint32_t v_u32    = smem_u32 + (uint32_t)SM_V * 4u;

    const uint32_t koff = (uint32_t)(r8 * KSTW + s4 * 8 + s3 * 4) * 4u;
    const uint32_t voff = (uint32_t)(r8 * VSTW + s4 * 8 + s3 * 4) * 4u;

    const __half* kg  = g_kth + base;    // [s][d]
    const __half* vtg = g_vth + base;    // [d][s]

    // ---- prologue loads: G0={K0}, G1={K1?} ----
    load_k_tile(kg, k_u32, tid);
    COMMIT();
    if (njt > 1) load_k_tile(kg + BC * D_, k_u32 + (uint32_t)KTILE_W * 4u, tid);
    COMMIT();

    // ---- Q: load, scale(+log2e), pack to half2 a-frags ----
    uint32_t qreg[8][4];
    {
        const float* qp = q + base;
        const long r0 = wrow + g, r1 = r0 + 8;
        #pragma unroll
        for (int ks = 0; ks < 8; ++ks) {
            int col = ks * 16 + 2 * c;
            qreg[ks][0] = pack2(qp[r0 * D_ + col]     * scale, qp[r0 * D_ + col + 1] * scale);
            qreg[ks][1] = pack2(qp[r1 * D_ + col]     * scale, qp[r1 * D_ + col + 1] * scale);
            qreg[ks][2] = pack2(qp[r0 * D_ + col + 8] * scale, qp[r0 * D_ + col + 9] * scale);
            qreg[ks][3] = pack2(qp[r1 * D_ + col + 8] * scale, qp[r1 * D_ + col + 9] * scale);
        }
    }

    float oacc[16][4];
    #pragma unroll
    for (int nt = 0; nt < 16; ++nt)
        oacc[nt][0] = oacc[nt][1] = oacc[nt][2] = oacc[nt][3] = 0.f;
    float m0 = -1e30f, m1 = -1e30f, l0 = 0.f, l1 = 0.f;
    float a0 = 0.f, a1 = 0.f;            // pending O-rescale factors
    uint32_t pa[4][4];                   // P a-frags of tile being PV'd
    float snxt[8][4], stmp[8][4];        // scores of tile j+1 / QK dest

    // ---- prologue compute: scores(0), softmax(0) -> pa ----
    WAIT1();            // G0 complete
    __syncthreads();
    qk_block(stmp, qreg, k_u32 + koff);
    softmax_tile(stmp, 0, wrow, g, c, m0, m1, l0, l1, a0, a1, pa);
    // (a0,a1 = ex2(-inf) = 0; oacc is zero so iter-0 rescale is a no-op)

    // ---- G2 = {K2?, V0} ----
    if (njt > 2) load_k_tile(kg + 2 * BC * D_, k_u32 + (uint32_t)(2 * KTILE_W) * 4u, tid);
    load_v_tile(vtg, v_u32, tid);
    COMMIT();
    WAIT1();            // G1 complete (K1)
    __syncthreads();
    if (njt > 1)
        qk_block(snxt, qreg, k_u32 + (uint32_t)KTILE_W * 4u + koff);

    // =================== main skewed loop ===================
    for (int j = 0; j < njt; ++j) {
        // issue loads for K(j+3), V(j+1); always commit (uniform wait count)
        if (j + 3 < njt)
            load_k_tile(kg + (long)(j + 3) * BC * D_,
                        k_u32 + (uint32_t)(((j + 3) % KSTAGES) * KTILE_W) * 4u, tid);
        if (j + 1 < njt)
            load_v_tile(vtg + (j + 1) * BC,
                        v_u32 + (uint32_t)(((j + 1) % VSTAGES) * VTILE_W) * 4u, tid);
        COMMIT();
        WAIT1();        // all but newest group done: K(j+2), V(j) arrived
        __syncthreads();

        // ---- 1. apply pending O rescale (from softmax(j)) ----
        #pragma unroll
        for (int nt = 0; nt < 16; ++nt) {
            oacc[nt][0] *= a0; oacc[nt][1] *= a0;
            oacc[nt][2] *= a1; oacc[nt][3] *= a1;
        }

        // ---- 2. PV(j): 32 LDSM + 64 MMA ----
        const uint32_t vtb = v_u32 + (uint32_t)((j % VSTAGES) * VTILE_W) * 4u + voff;
        #pragma unroll
        for (int nt = 0; nt < 16; ++nt) {
            const uint32_t vrow = vtb + (uint32_t)(nt * 8 * VSTW) * 4u;
            uint32_t b0, b1, b2, b3, b4, b5, b6, b7;
            ldsm4(b0, b1, b2, b3, vrow);
            ldsm4(b4, b5, b6, b7, vrow + 64u);
            mma_f16(oacc[nt], pa[0][0], pa[0][1], pa[0][2], pa[0][3], b0, b1);
            mma_f16(oacc[nt], pa[1][0], pa[1][1], pa[1][2], pa[1][3], b2, b3);
            mma_f16(oacc[nt], pa[2][0], pa[2][1], pa[2][2], pa[2][3], b4, b5);
            mma_f16(oacc[nt], pa[3][0], pa[3][1], pa[3][2], pa[3][3], b6, b7);
        }

        // ---- 3. QK(j+2): independent MMA burst ----
        if (j + 2 < njt)
            qk_block(stmp, qreg,
                     k_u32 + (uint32_t)(((j + 2) % KSTAGES) * KTILE_W) * 4u + koff);

        // ---- 4. softmax(j+1): scalar chain, overlaps 2 & 3 ----
        if (j + 1 < njt) {
            uint32_t pan[4][4];
            float a0n, a1n;
            softmax_tile(snxt, (j + 1) * BC, wrow, g, c,
                         m0, m1, l0, l1, a0n, a1n, pan);
            a0 = a0n; a1 = a1n;
            #pragma unroll
            for (int i = 0; i < 4; ++i) {
                pa[i][0] = pan[i][0]; pa[i][1] = pan[i][1];
                pa[i][2] = pan[i][2]; pa[i][3] = pan[i][3];
            }
            #pragma unroll
            for (int nt = 0; nt < 8; ++nt) {
                snxt[nt][0] = stmp[nt][0]; snxt[nt][1] = stmp[nt][1];
                snxt[nt][2] = stmp[nt][2]; snxt[nt][3] = stmp[nt][3];
            }
        }

        __syncthreads();   // guard smem ring reuse
    }

    // ---- epilogue: normalize and store ----
    const float inv0 = 1.f / l0, inv1 = 1.f / l1;
    float* op = out + base;
    const long r0 = wrow + g, r1 = r0 + 8;
    #pragma unroll
    for (int nt = 0; nt < 16; ++nt) {
        int col = nt * 8 + (c << 1);
        float2 o0 = make_float2(oacc[nt][0] * inv0, oacc[nt][1] * inv0);
        float2 o1 = make_float2(oacc[nt][2] * inv1, oacc[nt][3] * inv1);
        *(float2*)(op + r0 * D_ + col) = o0;
        *(float2*)(op + r1 * D_ + col) = o1;
    }
}

extern "C" void kernel_launch(void* const* d_in, const int* in_sizes, int n_in,
                              void* d_out, int out_size) {
    const float* q = (const float*)d_in[0];
    const float* k = (const float*)d_in[1];
    const float* v = (const float*)d_in[2];
    float* out = (float*)d_out;

    dim3 pgrid(S_ / 64, D_ / 64, B_ * H_);
    prep_kv_kernel<<<pgrid, 256>>>(v, (const float4*)k);

    cudaFuncSetAttribute(fa_skew_kernel,
                         cudaFuncAttributeMaxDynamicSharedMemorySize, SMEM_BYTES);
    dim3 grid(S_ / BR, B_ * H_);
    fa_skew_kernel<<<grid, THREADS, SMEM_BYTES>>>(q, out);
}